// round 3
// baseline (speedup 1.0000x reference)
#include <cuda_runtime.h>
#include <math.h>

#define BSZ 4
#define LSEQ 4096
#define DM 256
#define DI 512
#define MTOT (BSZ*LSEQ)        // 16384
#define NCHUNK 64
#define CLEN 64                // NCHUNK*CLEN = LSEQ

// ---------------- scratch (device globals; no allocations allowed) ---------
__device__ float g_xn[MTOT*DM];          // layernormed input (M,256)
__device__ float g_xf[MTOT*DM];          // raw xf in (M,C) layout (for skip add)
__device__ float g_xz[MTOT*2*DI];        // in_proj output (M,1024): [0:512)=xin, [512:1024)=z
__device__ float g_xc[MTOT*DI];          // conv+silu output (M,512)
__device__ float g_dbl[MTOT*48];         // x_proj output (M,48): dt16|B16|C16
__device__ float g_dt[MTOT*DI];          // dt (softplus) -> overwritten with chunk prefix sums
__device__ float g_y[MTOT*DI];           // scan output (local -> final gated)
__device__ float g_xm[MTOT*DM];          // out_proj + skip
__device__ float g_outl[MTOT*DM];        // final proj output, linear (M,C) layout
__device__ float g_hend[BSZ*NCHUNK*16*DI]; // chunk end states -> chunk incoming states

// ---------------- packed f32x2 helpers (sm_103a FFMA2) ----------------------
__device__ __forceinline__ unsigned long long pk2(float x) {
    unsigned long long r;
    unsigned int u = __float_as_uint(x);
    asm("mov.b64 %0, {%1, %1};" : "=l"(r) : "r"(u));
    return r;
}
__device__ __forceinline__ void ffma2(unsigned long long& d,
                                      unsigned long long a,
                                      unsigned long long b) {
    asm("fma.rn.f32x2 %0, %1, %2, %0;" : "+l"(d) : "l"(a), "l"(b));
}
__device__ __forceinline__ float2 unpk2(unsigned long long v) {
    unsigned int lo, hi;
    asm("mov.b64 {%0, %1}, %2;" : "=r"(lo), "=r"(hi) : "l"(v));
    return make_float2(__uint_as_float(lo), __uint_as_float(hi));
}

// ---------------- LayerNorm: x (B,C,L) -> xn (B*L, C), also xf copy --------
__global__ void ln_kernel(const float* __restrict__ x,
                          const float* __restrict__ nw,
                          const float* __restrict__ nb) {
    __shared__ float s[256*33];
    __shared__ float ps[8][33], pq[8][33];
    __shared__ float s_mu[32], s_rs[32];
    int blk = blockIdx.x;            // 512 blocks, 32 l-positions each
    int b  = blk >> 7;
    int l0 = (blk & 127) * 32;
    int tid = threadIdx.x;           // 256
    int lx = tid & 31, cy = tid >> 5;
    const float* xb = x + (size_t)b * DM * LSEQ;
    #pragma unroll 4
    for (int cb = 0; cb < 256; cb += 8) {
        int c = cb + cy;
        s[c*33 + lx] = xb[(size_t)c * LSEQ + l0 + lx];
    }
    __syncthreads();
    {
        float sum = 0.f, sq = 0.f;
        int c0 = cy * 32;
        #pragma unroll 8
        for (int c = c0; c < c0 + 32; c++) { float v = s[c*33 + lx]; sum += v; sq += v*v; }
        ps[cy][lx] = sum; pq[cy][lx] = sq;
    }
    __syncthreads();
    if (tid < 32) {
        float sum = 0.f, sq = 0.f;
        #pragma unroll
        for (int p = 0; p < 8; p++) { sum += ps[p][tid]; sq += pq[p][tid]; }
        float mu = sum * (1.f/256.f);
        float var = sq * (1.f/256.f) - mu*mu;
        s_mu[tid] = mu;
        s_rs[tid] = rsqrtf(var + 1e-5f);
    }
    __syncthreads();
    for (int j = tid; j < 32*256; j += 256) {
        int ll = j >> 8, c = j & 255;
        float v = s[c*33 + ll];
        size_t idx = (size_t)(b*LSEQ + l0 + ll)*DM + c;
        g_xf[idx] = v;
        g_xn[idx] = (v - s_mu[ll]) * s_rs[ll] * nw[c] + nb[c];
    }
}

// ---------------- generic 128x128 SGEMM (FFMA2): C = A @ W^T (+ epilogue) --
// MODE 0: A=g_xn (K=256)  W=in_proj_w  -> g_xz                    (N=1024)
// MODE 1: A=g_y  (K=512)  W=out_proj_w -> g_xm = acc + skip*g_xf  (N=256)
// MODE 2: A=g_xm (K=256)  W=proj_w     -> g_outl = acc + bias[n]  (N=256)
template<int MODE, int N, int K>
__global__ __launch_bounds__(256)
void gemm128(const float* __restrict__ W, float* __restrict__ Cout,
             const float* __restrict__ extra, const float* __restrict__ skipPtr) {
    const float* A = (MODE == 0) ? g_xn : (MODE == 1) ? g_y : g_xm;
    __shared__ float As[16][132];
    __shared__ float Bs[16][132];
    int tid = threadIdx.x;
    int m0 = blockIdx.y * 128, n0 = blockIdx.x * 128;
    int ty = tid >> 4, tx = tid & 15;
    unsigned long long acc[8][4];
    #pragma unroll
    for (int i = 0; i < 8; i++)
        #pragma unroll
        for (int j = 0; j < 4; j++) acc[i][j] = 0ULL;

    int lr = tid >> 1, lk = (tid & 1) * 4;
    const float* Ap = A + (size_t)(m0 + lr) * K + lk;
    const float* Wp = W + (size_t)(n0 + lr) * K + lk;

    float4 a0v = *(const float4*)(Ap);
    float4 a1v = *(const float4*)(Ap + 8);
    float4 w0v = *(const float4*)(Wp);
    float4 w1v = *(const float4*)(Wp + 8);

    for (int k0 = 0; k0 < K; k0 += 16) {
        As[lk+0][lr] = a0v.x; As[lk+1][lr] = a0v.y; As[lk+2][lr] = a0v.z; As[lk+3][lr] = a0v.w;
        As[lk+8][lr] = a1v.x; As[lk+9][lr] = a1v.y; As[lk+10][lr] = a1v.z; As[lk+11][lr] = a1v.w;
        Bs[lk+0][lr] = w0v.x; Bs[lk+1][lr] = w0v.y; Bs[lk+2][lr] = w0v.z; Bs[lk+3][lr] = w0v.w;
        Bs[lk+8][lr] = w1v.x; Bs[lk+9][lr] = w1v.y; Bs[lk+10][lr] = w1v.z; Bs[lk+11][lr] = w1v.w;
        __syncthreads();
        if (k0 + 16 < K) {
            a0v = *(const float4*)(Ap + k0 + 16);
            a1v = *(const float4*)(Ap + k0 + 24);
            w0v = *(const float4*)(Wp + k0 + 16);
            w1v = *(const float4*)(Wp + k0 + 24);
        }
        #pragma unroll
        for (int kk = 0; kk < 16; kk++) {
            float4 fa0 = *(const float4*)&As[kk][ty*8];
            float4 fa1 = *(const float4*)&As[kk][ty*8+4];
            ulonglong2 bq0 = *(const ulonglong2*)&Bs[kk][tx*8];
            ulonglong2 bq1 = *(const ulonglong2*)&Bs[kk][tx*8+4];
            unsigned long long bb[4] = {bq0.x, bq0.y, bq1.x, bq1.y};
            float av[8] = {fa0.x,fa0.y,fa0.z,fa0.w,fa1.x,fa1.y,fa1.z,fa1.w};
            #pragma unroll
            for (int i = 0; i < 8; i++) {
                unsigned long long ap = pk2(av[i]);
                #pragma unroll
                for (int j = 0; j < 4; j++) ffma2(acc[i][j], ap, bb[j]);
            }
        }
        __syncthreads();
    }

    float skip = 0.f;
    if (MODE == 1) skip = skipPtr[0];
    #pragma unroll
    for (int i = 0; i < 8; i++) {
        int m = m0 + ty*8 + i;
        #pragma unroll
        for (int j = 0; j < 4; j++) {
            int n = n0 + tx*8 + 2*j;
            float2 v = unpk2(acc[i][j]);
            if (MODE == 0) {
                g_xz[(size_t)m * N + n]     = v.x;
                g_xz[(size_t)m * N + n + 1] = v.y;
            } else if (MODE == 1) {
                g_xm[(size_t)m * 256 + n]     = v.x + skip * g_xf[(size_t)m*256 + n];
                g_xm[(size_t)m * 256 + n + 1] = v.y + skip * g_xf[(size_t)m*256 + n + 1];
            } else {
                g_outl[(size_t)m * 256 + n]     = v.x + extra[n];
                g_outl[(size_t)m * 256 + n + 1] = v.y + extra[n+1];
            }
        }
    }
}

// ---------------- output transpose: g_outl (B,L,C) -> out (B,C,L) ----------
__global__ __launch_bounds__(256)
void outtr_kernel(float* __restrict__ out) {
    __shared__ float t[32][33];
    int lt = blockIdx.x * 32;
    int ct = blockIdx.y * 32;
    int b  = blockIdx.z;
    int tx = threadIdx.x & 31, ty = threadIdx.x >> 5;  // ty 0..7
    #pragma unroll
    for (int p = 0; p < 4; p++) {
        int l = lt + ty + p*8;
        t[ty + p*8][tx] = g_outl[(size_t)(b*4096 + l)*256 + ct + tx];
    }
    __syncthreads();
    #pragma unroll
    for (int p = 0; p < 4; p++) {
        int c = ct + ty + p*8;
        out[(size_t)(b*256 + c)*4096 + lt + tx] = t[tx][ty + p*8];
    }
}

// ---------------- depthwise causal conv (k=4) + SiLU, 8 rows/block ---------
__global__ void conv_kernel(const float* __restrict__ cw, const float* __restrict__ cb) {
    int d = threadIdx.x;          // 512
    int m0 = blockIdx.x * 8;      // 2048 blocks
    int l0 = m0 & 4095;
    float w0 = cw[d*4+0], w1 = cw[d*4+1], w2 = cw[d*4+2], w3 = cw[d*4+3];
    float bias = cb[d];
    float r[11];
    #pragma unroll
    for (int i = 0; i < 11; i++) {
        int off = i - 3;
        r[i] = (l0 + off >= 0) ? g_xz[(size_t)(m0 + off)*1024 + d] : 0.f;
    }
    #pragma unroll
    for (int j = 0; j < 8; j++) {
        float acc = bias;
        acc = fmaf(r[j],   w0, acc);
        acc = fmaf(r[j+1], w1, acc);
        acc = fmaf(r[j+2], w2, acc);
        acc = fmaf(r[j+3], w3, acc);
        float sg = 1.f / (1.f + __expf(-acc));
        g_xc[(size_t)(m0+j)*512 + d] = acc * sg;
    }
}

// ---------------- x_proj: dbl = xc @ x_proj_w^T  (M=16384, N=48, K=512) ----
// 256 threads, M-tile 64. Thread = 1 row x 12 n (FFMA2 pairs).
__global__ __launch_bounds__(256)
void xproj_kernel(const float* __restrict__ Wp) {
    __shared__ float As[64][65];   // [k][row]
    __shared__ float Ws[64][52];   // [k][n] (row 208B, 16B-multiple)
    int tid = threadIdx.x;              // 256
    int m0 = blockIdx.x * 64;           // 256 blocks
    int row = tid >> 2;                 // 0..63
    int ng  = (tid & 3) * 12;           // 0,12,24,36
    unsigned long long acc[6];
    #pragma unroll
    for (int j = 0; j < 6; j++) acc[j] = 0ULL;

    for (int k0 = 0; k0 < 512; k0 += 64) {
        __syncthreads();
        // A tile: 64 rows x 64 k, transposed. 1024 float4 / 256 thr = 4 each.
        #pragma unroll
        for (int jj = 0; jj < 4; jj++) {
            int idx = tid + jj*256;
            int r = idx >> 4, kq = (idx & 15) * 4;
            float4 v = *(const float4*)&g_xc[(size_t)(m0+r)*512 + k0 + kq];
            As[kq+0][r] = v.x; As[kq+1][r] = v.y; As[kq+2][r] = v.z; As[kq+3][r] = v.w;
        }
        // W tile: 48 n x 64 k -> Ws[k][n]. 3072 / 256 = 12 each.
        #pragma unroll
        for (int jj = 0; jj < 12; jj++) {
            int i = tid + jj*256;
            int k = i & 63, n = i >> 6;
            Ws[k][n] = Wp[(size_t)n*512 + k0 + k];
        }
        __syncthreads();
        #pragma unroll 16
        for (int k = 0; k < 64; k++) {
            unsigned long long ap = pk2(As[k][row]);
            ulonglong2 w0 = *(const ulonglong2*)&Ws[k][ng];
            ulonglong2 w1 = *(const ulonglong2*)&Ws[k][ng+4];
            ulonglong2 w2 = *(const ulonglong2*)&Ws[k][ng+8];
            ffma2(acc[0], ap, w0.x);
            ffma2(acc[1], ap, w0.y);
            ffma2(acc[2], ap, w1.x);
            ffma2(acc[3], ap, w1.y);
            ffma2(acc[4], ap, w2.x);
            ffma2(acc[5], ap, w2.y);
        }
    }
    #pragma unroll
    for (int j = 0; j < 6; j++) {
        float2 v = unpk2(acc[j]);
        g_dbl[(size_t)(m0+row)*48 + ng + 2*j]     = v.x;
        g_dbl[(size_t)(m0+row)*48 + ng + 2*j + 1] = v.y;
    }
}

// ---------------- dt = softplus(dt_raw @ dt_proj_w^T + b) ------------------
__global__ void dt_kernel(const float* __restrict__ Wd, const float* __restrict__ bd) {
    __shared__ float sw[16*512];
    __shared__ float sb[512];
    int tid = threadIdx.x;  // 512
    for (int i = tid; i < 8192; i += 512) {
        int d = i >> 4, r = i & 15;
        sw[r*512 + d] = Wd[i];
    }
    sb[tid] = bd[tid];
    __syncthreads();
    int mbase = blockIdx.x * 8;
    for (int mi = 0; mi < 8; mi++) {
        int m = mbase + mi;
        float acc = sb[tid];
        const float* dr = g_dbl + (size_t)m*48;
        #pragma unroll
        for (int r = 0; r < 16; r++) acc = fmaf(dr[r], sw[r*512 + tid], acc);
        g_dt[(size_t)m*512 + tid] = (acc > 20.f) ? acc : __logf(1.f + __expf(acc));
    }
}

// ---------------- scan phase 1: per-chunk local recurrence (h0=0) ----------
__global__ void scan1_kernel(const float* __restrict__ A_log) {
    __shared__ float sbc[2][32];
    int ch = blockIdx.x, b = blockIdx.y, g = blockIdx.z;
    int tid = threadIdx.x;            // 128
    int d = g*128 + tid;
    float a[16], h[16];
    #pragma unroll
    for (int n = 0; n < 16; n++) { a[n] = -expf(A_log[d*16 + n]); h[n] = 0.f; }
    int mbase = b*LSEQ + ch*CLEN;
    if (tid < 32) sbc[0][tid] = g_dbl[(size_t)mbase*48 + 16 + tid];
    float S = 0.f;
    float u   = g_xc[(size_t)mbase*512 + d];
    float dtv = g_dt[(size_t)mbase*512 + d];
    for (int i = 0; i < CLEN; i++) {
        __syncthreads();
        float u_n = 0.f, dt_n = 0.f;
        if (i < CLEN-1) {
            if (tid < 32) sbc[(i+1)&1][tid] = g_dbl[(size_t)(mbase+i+1)*48 + 16 + tid];
            u_n  = g_xc[(size_t)(mbase+i+1)*512 + d];
            dt_n = g_dt[(size_t)(mbase+i+1)*512 + d];
        }
        int m = mbase + i;
        S += dtv;
        g_dt[(size_t)m*512 + d] = S;
        float du = dtv * u;
        const float* sB = sbc[i&1];
        const float* sC = sbc[i&1] + 16;
        float y = 0.f;
        #pragma unroll
        for (int n = 0; n < 16; n++) {
            float dA = __expf(dtv * a[n]);
            h[n] = fmaf(h[n], dA, du * sB[n]);
            y = fmaf(h[n], sC[n], y);
        }
        g_y[(size_t)m*512 + d] = y;
        u = u_n; dtv = dt_n;
    }
    size_t base = (size_t)((b*NCHUNK + ch)*16) * 512 + d;
    #pragma unroll
    for (int n = 0; n < 16; n++) g_hend[base + (size_t)n*512] = h[n];
}

// ---------------- scan phase 2: propagate states across chunks -------------
__global__ void scan2_kernel(const float* __restrict__ A_log) {
    int n = blockIdx.x, b = blockIdx.y, d = threadIdx.x;  // 16 x 4, 512
    float an = -expf(A_log[d*16 + n]);
    float hprev = 0.f;
    for (int ch = 0; ch < NCHUNK; ch++) {
        float Send = g_dt[(size_t)(b*LSEQ + ch*CLEN + CLEN-1)*512 + d];
        size_t idx = (size_t)((b*NCHUNK + ch)*16 + n)*512 + d;
        float tmp = g_hend[idx];
        g_hend[idx] = hprev;
        hprev = fmaf(__expf(an * Send), hprev, tmp);
    }
}

// ---------------- scan phase 3: fix-up + D skip + z gating ------------------
__global__ void scan3_kernel(const float* __restrict__ A_log,
                             const float* __restrict__ Dp) {
    __shared__ float sc[2][16];
    int ch = blockIdx.x, b = blockIdx.y, g = blockIdx.z;
    int tid = threadIdx.x;            // 128
    int d = g*128 + tid;
    float a[16], hin[16];
    size_t hbase = (size_t)((b*NCHUNK + ch)*16) * 512 + d;
    #pragma unroll
    for (int n = 0; n < 16; n++) {
        a[n]   = -expf(A_log[d*16 + n]);
        hin[n] = g_hend[hbase + (size_t)n*512];
    }
    float Dd = Dp[d];
    int mbase = b*LSEQ + ch*CLEN;
    if (tid < 16) sc[0][tid] = g_dbl[(size_t)mbase*48 + 32 + tid];
    float S  = g_dt[(size_t)mbase*512 + d];
    float u  = g_xc[(size_t)mbase*512 + d];
    float z  = g_xz[(size_t)mbase*1024 + 512 + d];
    float yl = g_y[(size_t)mbase*512 + d];
    for (int i = 0; i < CLEN; i++) {
        __syncthreads();
        float S_n=0.f, u_n=0.f, z_n=0.f, yl_n=0.f;
        if (i < CLEN-1) {
            if (tid < 16) sc[(i+1)&1][tid] = g_dbl[(size_t)(mbase+i+1)*48 + 32 + tid];
            S_n  = g_dt[(size_t)(mbase+i+1)*512 + d];
            u_n  = g_xc[(size_t)(mbase+i+1)*512 + d];
            z_n  = g_xz[(size_t)(mbase+i+1)*1024 + 512 + d];
            yl_n = g_y[(size_t)(mbase+i+1)*512 + d];
        }
        int m = mbase + i;
        const float* C = sc[i&1];
        float yf = 0.f;
        #pragma unroll
        for (int n = 0; n < 16; n++)
            yf = fmaf(C[n] * __expf(a[n]*S), hin[n], yf);
        float y = yl + yf + u*Dd;
        y *= z / (1.f + __expf(-z));   // * silu(z)
        g_y[(size_t)m*512 + d] = y;
        S = S_n; u = u_n; z = z_n; yl = yl_n;
    }
}

// ---------------------------------------------------------------------------
extern "C" void kernel_launch(void* const* d_in, const int* in_sizes, int n_in,
                              void* d_out, int out_size) {
    const float* x         = (const float*)d_in[0];
    const float* norm_w    = (const float*)d_in[1];
    const float* norm_b    = (const float*)d_in[2];
    const float* in_proj_w = (const float*)d_in[3];
    const float* conv_w    = (const float*)d_in[4];
    const float* conv_b    = (const float*)d_in[5];
    const float* x_proj_w  = (const float*)d_in[6];
    const float* dt_proj_w = (const float*)d_in[7];
    const float* dt_proj_b = (const float*)d_in[8];
    const float* A_log     = (const float*)d_in[9];
    const float* D_ssm     = (const float*)d_in[10];
    const float* out_proj_w= (const float*)d_in[11];
    const float* proj_w    = (const float*)d_in[12];
    const float* proj_b    = (const float*)d_in[13];
    const float* skip      = (const float*)d_in[14];
    float* out = (float*)d_out;

    ln_kernel<<<512, 256>>>(x, norm_w, norm_b);
    gemm128<0,1024,256><<<dim3(8,128), 256>>>(in_proj_w, nullptr, nullptr, nullptr);
    conv_kernel<<<2048, 512>>>(conv_w, conv_b);
    xproj_kernel<<<256, 256>>>(x_proj_w);
    dt_kernel<<<2048, 512>>>(dt_proj_w, dt_proj_b);
    scan1_kernel<<<dim3(NCHUNK,BSZ,4), 128>>>(A_log);
    scan2_kernel<<<dim3(16,BSZ), 512>>>(A_log);
    scan3_kernel<<<dim3(NCHUNK,BSZ,4), 128>>>(A_log, D_ssm);
    gemm128<1,256,512><<<dim3(2,128), 256>>>(out_proj_w, nullptr, nullptr, skip);
    gemm128<2,256,256><<<dim3(2,128), 256>>>(proj_w, nullptr, proj_b, nullptr);
    outtr_kernel<<<dim3(128,8,4), 256>>>(out);
}

// round 5
// speedup vs baseline: 1.6263x; 1.6263x over previous
#include <cuda_runtime.h>
#include <cuda_bf16.h>
#include <math.h>
#include <stdint.h>

#define BSZ 4
#define LSEQ 4096
#define DM 256
#define DI 512
#define MTOT (BSZ*LSEQ)        // 16384
#define NCHUNK 64
#define CLEN 64

// ---------------- scratch (device globals; no allocations allowed) ---------
__device__ float g_xn[MTOT*DM];
__device__ float g_xf[MTOT*DM];
__device__ float g_xz[MTOT*2*DI];
__device__ float g_xc[MTOT*DI];
__device__ float g_dbl[MTOT*48];
__device__ float g_dt[MTOT*DI];
__device__ float g_y[MTOT*DI];
__device__ float g_xm[MTOT*DM];
__device__ float g_outl[MTOT*DM];
__device__ float g_hend[BSZ*NCHUNK*16*DI];

// ---------------- helpers ----------------------------------------------------
__device__ __forceinline__ uint32_t smem_u32(const void* p) {
    uint32_t a;
    asm("{ .reg .u64 t; cvta.to.shared.u64 t, %1; cvt.u32.u64 %0, t; }" : "=r"(a) : "l"(p));
    return a;
}
// split fp32x4 -> hi/lo bf16x2 pairs
__device__ __forceinline__ void split4(float4 v, uint2& h, uint2& l) {
    __nv_bfloat16 h0 = __float2bfloat16(v.x), h1 = __float2bfloat16(v.y);
    __nv_bfloat16 h2 = __float2bfloat16(v.z), h3 = __float2bfloat16(v.w);
    float r0 = v.x - __bfloat162float(h0), r1 = v.y - __bfloat162float(h1);
    float r2 = v.z - __bfloat162float(h2), r3 = v.w - __bfloat162float(h3);
    __nv_bfloat16 l0 = __float2bfloat16(r0), l1 = __float2bfloat16(r1);
    __nv_bfloat16 l2 = __float2bfloat16(r2), l3 = __float2bfloat16(r3);
    h.x = ((uint32_t)__bfloat16_as_ushort(h1) << 16) | __bfloat16_as_ushort(h0);
    h.y = ((uint32_t)__bfloat16_as_ushort(h3) << 16) | __bfloat16_as_ushort(h2);
    l.x = ((uint32_t)__bfloat16_as_ushort(l1) << 16) | __bfloat16_as_ushort(l0);
    l.y = ((uint32_t)__bfloat16_as_ushort(l3) << 16) | __bfloat16_as_ushort(l2);
}
__device__ __forceinline__ void ldm4(uint32_t* r, uint32_t addr) {
    asm volatile("ldmatrix.sync.aligned.m8n8.x4.shared.b16 {%0,%1,%2,%3}, [%4];"
        : "=r"(r[0]), "=r"(r[1]), "=r"(r[2]), "=r"(r[3]) : "r"(addr));
}
__device__ __forceinline__ void mma16816(float* c, const uint32_t* a,
                                         uint32_t b0, uint32_t b1) {
    asm volatile(
        "mma.sync.aligned.m16n8k16.row.col.f32.bf16.bf16.f32 "
        "{%0,%1,%2,%3}, {%4,%5,%6,%7}, {%8,%9}, {%0,%1,%2,%3};"
        : "+f"(c[0]), "+f"(c[1]), "+f"(c[2]), "+f"(c[3])
        : "r"(a[0]), "r"(a[1]), "r"(a[2]), "r"(a[3]), "r"(b0), "r"(b1));
}

// ======== warp-MMA GEMM: C = A @ W^T, 128x128 CTA tile, split-bf16 x3 =======
// MODE 0: A=g_xn (K=256) -> g_xz (N=1024)
// MODE 1: A=g_y  (K=512) -> g_xm = acc + skip*g_xf (N=256)
// MODE 2: A=g_xm (K=256) -> g_outl = acc + bias[n] (N=256)
// smem stage: A_hi(10240) A_lo(10240) B_hi(10240) B_lo(10240) = 40960; x2 stages
#define GSTAGE 40960
#define GEMM_SMEM (2*GSTAGE)
#define KC 32
#define SROW 80     // bytes per smem row: (32+8) bf16

template<int MODE, int N, int K>
__global__ __launch_bounds__(256)
void gemm_mma(const float* __restrict__ W, const float* __restrict__ extra,
              const float* __restrict__ skipPtr) {
    extern __shared__ char sm[];
    const float* A = (MODE == 0) ? g_xn : (MODE == 1) ? g_y : g_xm;
    uint32_t sbase = smem_u32(sm);
    int tid = threadIdx.x, wid = tid >> 5, lane = tid & 31;
    int warp_m = wid & 3, warp_n = wid >> 2;
    int m0 = blockIdx.y * 128, n0 = blockIdx.x * 128;

    float acc[2][8][4];
    #pragma unroll
    for (int mt = 0; mt < 2; mt++)
        #pragma unroll
        for (int nt = 0; nt < 8; nt++)
            #pragma unroll
            for (int q = 0; q < 4; q++) acc[mt][nt][q] = 0.f;

    float4 ra[4], rb[4];
    const int row_ld = tid >> 3;              // 0..31 (x4 iterations -> 128 rows)
    const int c4 = (tid & 7) << 2;            // 0,4,...,28

    // prologue: load + store chunk 0
    #pragma unroll
    for (int t = 0; t < 4; t++) {
        int row = row_ld + t * 32;
        ra[t] = *(const float4*)&A[(size_t)(m0 + row) * K + c4];
        rb[t] = *(const float4*)&W[(size_t)(n0 + row) * K + c4];
    }
    #pragma unroll
    for (int t = 0; t < 4; t++) {
        int row = row_ld + t * 32;
        uint2 h, l;
        split4(ra[t], h, l);
        *(uint2*)(sm + row * SROW + c4 * 2) = h;
        *(uint2*)(sm + 10240 + row * SROW + c4 * 2) = l;
        split4(rb[t], h, l);
        *(uint2*)(sm + 20480 + row * SROW + c4 * 2) = h;
        *(uint2*)(sm + 30720 + row * SROW + c4 * 2) = l;
    }

    const int NKC = K / KC;
    // ldmatrix lane-address components
    const int a_row = (lane & 7) + ((lane >> 3) & 1) * 8;
    const int a_koff = ((lane >> 4) & 1) * 16;
    const int b_row = (lane & 7) + ((lane >> 4) & 1) * 8;
    const int b_koff = ((lane >> 3) & 1) * 16;

    for (int kc = 0; kc < NKC; kc++) {
        __syncthreads();
        if (kc + 1 < NKC) {
            int k0 = (kc + 1) * KC;
            #pragma unroll
            for (int t = 0; t < 4; t++) {
                int row = row_ld + t * 32;
                ra[t] = *(const float4*)&A[(size_t)(m0 + row) * K + k0 + c4];
                rb[t] = *(const float4*)&W[(size_t)(n0 + row) * K + k0 + c4];
            }
        }
        uint32_t aB = sbase + (kc & 1) * GSTAGE;
        uint32_t bB = aB + 20480;
        #pragma unroll
        for (int kk = 0; kk < 2; kk++) {
            uint32_t Ah[2][4], Al[2][4], Bh[4][4], Bl[4][4];
            #pragma unroll
            for (int mt = 0; mt < 2; mt++) {
                uint32_t addr = aB + (uint32_t)((warp_m * 32 + mt * 16 + a_row) * SROW
                                               + kk * 32 + a_koff);
                ldm4(Ah[mt], addr);
                ldm4(Al[mt], addr + 10240);
            }
            #pragma unroll
            for (int np = 0; np < 4; np++) {
                uint32_t addr = bB + (uint32_t)((warp_n * 64 + np * 16 + b_row) * SROW
                                               + kk * 32 + b_koff);
                ldm4(Bh[np], addr);
                ldm4(Bl[np], addr + 10240);
            }
            #pragma unroll
            for (int mt = 0; mt < 2; mt++)
                #pragma unroll
                for (int nt = 0; nt < 8; nt++) {
                    int np = nt >> 1, o = (nt & 1) * 2;
                    mma16816(acc[mt][nt], Ah[mt], Bh[np][o], Bh[np][o + 1]);
                    mma16816(acc[mt][nt], Ah[mt], Bl[np][o], Bl[np][o + 1]);
                    mma16816(acc[mt][nt], Al[mt], Bh[np][o], Bh[np][o + 1]);
                }
        }
        if (kc + 1 < NKC) {
            char* dst = sm + ((kc + 1) & 1) * GSTAGE;
            #pragma unroll
            for (int t = 0; t < 4; t++) {
                int row = row_ld + t * 32;
                uint2 h, l;
                split4(ra[t], h, l);
                *(uint2*)(dst + row * SROW + c4 * 2) = h;
                *(uint2*)(dst + 10240 + row * SROW + c4 * 2) = l;
                split4(rb[t], h, l);
                *(uint2*)(dst + 20480 + row * SROW + c4 * 2) = h;
                *(uint2*)(dst + 30720 + row * SROW + c4 * 2) = l;
            }
        }
    }

    // ---- epilogue: fragments -> global (row-major) ----
    float skip = (MODE == 1) ? skipPtr[0] : 0.f;
    #pragma unroll
    for (int mt = 0; mt < 2; mt++) {
        #pragma unroll
        for (int nt = 0; nt < 8; nt++) {
            int row = m0 + warp_m * 32 + mt * 16 + (lane >> 2);
            int col = n0 + warp_n * 64 + nt * 8 + (lane & 3) * 2;
            float2 v0 = make_float2(acc[mt][nt][0], acc[mt][nt][1]);
            float2 v1 = make_float2(acc[mt][nt][2], acc[mt][nt][3]);
            if (MODE == 0) {
                *(float2*)&g_xz[(size_t)row * N + col] = v0;
                *(float2*)&g_xz[(size_t)(row + 8) * N + col] = v1;
            } else if (MODE == 1) {
                float2 f0 = *(const float2*)&g_xf[(size_t)row * 256 + col];
                float2 f1 = *(const float2*)&g_xf[(size_t)(row + 8) * 256 + col];
                v0.x += skip * f0.x; v0.y += skip * f0.y;
                v1.x += skip * f1.x; v1.y += skip * f1.y;
                *(float2*)&g_xm[(size_t)row * 256 + col] = v0;
                *(float2*)&g_xm[(size_t)(row + 8) * 256 + col] = v1;
            } else {
                float2 bia = *(const float2*)&extra[col];
                v0.x += bia.x; v0.y += bia.y;
                v1.x += bia.x; v1.y += bia.y;
                *(float2*)&g_outl[(size_t)row * 256 + col] = v0;
                *(float2*)&g_outl[(size_t)(row + 8) * 256 + col] = v1;
            }
        }
    }
}

// ---------------- LayerNorm: x (B,C,L) -> xn (B*L, C), also xf copy --------
__global__ void ln_kernel(const float* __restrict__ x,
                          const float* __restrict__ nw,
                          const float* __restrict__ nb) {
    __shared__ float s[256*33];
    __shared__ float ps[8][33], pq[8][33];
    __shared__ float s_mu[32], s_rs[32];
    int blk = blockIdx.x;
    int b  = blk >> 7;
    int l0 = (blk & 127) * 32;
    int tid = threadIdx.x;
    int lx = tid & 31, cy = tid >> 5;
    const float* xb = x + (size_t)b * DM * LSEQ;
    #pragma unroll 4
    for (int cb = 0; cb < 256; cb += 8) {
        int c = cb + cy;
        s[c*33 + lx] = xb[(size_t)c * LSEQ + l0 + lx];
    }
    __syncthreads();
    {
        float sum = 0.f, sq = 0.f;
        int c0 = cy * 32;
        #pragma unroll 8
        for (int c = c0; c < c0 + 32; c++) { float v = s[c*33 + lx]; sum += v; sq += v*v; }
        ps[cy][lx] = sum; pq[cy][lx] = sq;
    }
    __syncthreads();
    if (tid < 32) {
        float sum = 0.f, sq = 0.f;
        #pragma unroll
        for (int p = 0; p < 8; p++) { sum += ps[p][tid]; sq += pq[p][tid]; }
        float mu = sum * (1.f/256.f);
        float var = sq * (1.f/256.f) - mu*mu;
        s_mu[tid] = mu;
        s_rs[tid] = rsqrtf(var + 1e-5f);
    }
    __syncthreads();
    for (int j = tid; j < 32*256; j += 256) {
        int ll = j >> 8, c = j & 255;
        float v = s[c*33 + ll];
        size_t idx = (size_t)(b*LSEQ + l0 + ll)*DM + c;
        g_xf[idx] = v;
        g_xn[idx] = (v - s_mu[ll]) * s_rs[ll] * nw[c] + nb[c];
    }
}

// ---------------- output transpose: g_outl (B,L,C) -> out (B,C,L) ----------
__global__ __launch_bounds__(256)
void outtr_kernel(float* __restrict__ out) {
    __shared__ float t[32][33];
    int lt = blockIdx.x * 32;
    int ct = blockIdx.y * 32;
    int b  = blockIdx.z;
    int tx = threadIdx.x & 31, ty = threadIdx.x >> 5;
    #pragma unroll
    for (int p = 0; p < 4; p++) {
        int l = lt + ty + p*8;
        t[ty + p*8][tx] = g_outl[(size_t)(b*4096 + l)*256 + ct + tx];
    }
    __syncthreads();
    #pragma unroll
    for (int p = 0; p < 4; p++) {
        int c = ct + ty + p*8;
        out[(size_t)(b*256 + c)*4096 + lt + tx] = t[tx][ty + p*8];
    }
}

// ---------------- depthwise causal conv (k=4) + SiLU, 8 rows/block ---------
__global__ void conv_kernel(const float* __restrict__ cw, const float* __restrict__ cb) {
    int d = threadIdx.x;
    int m0 = blockIdx.x * 8;
    int l0 = m0 & 4095;
    float w0 = cw[d*4+0], w1 = cw[d*4+1], w2 = cw[d*4+2], w3 = cw[d*4+3];
    float bias = cb[d];
    float r[11];
    #pragma unroll
    for (int i = 0; i < 11; i++) {
        int off = i - 3;
        r[i] = (l0 + off >= 0) ? g_xz[(size_t)(m0 + off)*1024 + d] : 0.f;
    }
    #pragma unroll
    for (int j = 0; j < 8; j++) {
        float acc = bias;
        acc = fmaf(r[j],   w0, acc);
        acc = fmaf(r[j+1], w1, acc);
        acc = fmaf(r[j+2], w2, acc);
        acc = fmaf(r[j+3], w3, acc);
        float sg = 1.f / (1.f + __expf(-acc));
        g_xc[(size_t)(m0+j)*512 + d] = acc * sg;
    }
}

// ---------------- x_proj: dbl = xc @ x_proj_w^T  (M=16384, N=48, K=512) ----
// (round-2 proven version: 128 thr, M-tile 64, 2 rows x 12 n, plain fmaf)
__global__ __launch_bounds__(128)
void xproj_kernel(const float* __restrict__ Wp) {
    __shared__ float As[64][66];   // [k][row]
    __shared__ float Ws[64][52];   // [k][n]
    int tid = threadIdx.x;              // 128
    int m0 = blockIdx.x * 64;           // 256 blocks
    int row0 = (tid >> 2) * 2;          // 0..62 even
    int ng   = (tid & 3) * 12;
    float acc0[12], acc1[12];
    #pragma unroll
    for (int j = 0; j < 12; j++) { acc0[j] = 0.f; acc1[j] = 0.f; }

    for (int k0 = 0; k0 < 512; k0 += 64) {
        __syncthreads();
        #pragma unroll
        for (int jj = 0; jj < 8; jj++) {
            int idx = tid + jj*128;
            int r = idx >> 4, kq = (idx & 15) * 4;
            float4 v = *(const float4*)&g_xc[(size_t)(m0+r)*512 + k0 + kq];
            As[kq+0][r] = v.x; As[kq+1][r] = v.y; As[kq+2][r] = v.z; As[kq+3][r] = v.w;
        }
        #pragma unroll
        for (int jj = 0; jj < 24; jj++) {
            int i = tid + jj*128;
            int k = i & 63, n = i >> 6;
            Ws[k][n] = Wp[(size_t)n*512 + k0 + k];
        }
        __syncthreads();
        #pragma unroll 16
        for (int k = 0; k < 64; k++) {
            float2 a = *(const float2*)&As[k][row0];
            float4 wA = *(const float4*)&Ws[k][ng];
            float4 wB = *(const float4*)&Ws[k][ng+4];
            float4 wC = *(const float4*)&Ws[k][ng+8];
            float w[12] = {wA.x,wA.y,wA.z,wA.w, wB.x,wB.y,wB.z,wB.w, wC.x,wC.y,wC.z,wC.w};
            #pragma unroll
            for (int j = 0; j < 12; j++) {
                acc0[j] = fmaf(a.x, w[j], acc0[j]);
                acc1[j] = fmaf(a.y, w[j], acc1[j]);
            }
        }
    }
    #pragma unroll
    for (int j = 0; j < 12; j++) {
        g_dbl[(size_t)(m0+row0  )*48 + ng + j] = acc0[j];
        g_dbl[(size_t)(m0+row0+1)*48 + ng + j] = acc1[j];
    }
}

// ---------------- dt = softplus(dt_raw @ dt_proj_w^T + b) ------------------
__global__ void dt_kernel(const float* __restrict__ Wd, const float* __restrict__ bd) {
    __shared__ float sw[16*512];
    __shared__ float sb[512];
    int tid = threadIdx.x;
    for (int i = tid; i < 8192; i += 512) {
        int d = i >> 4, r = i & 15;
        sw[r*512 + d] = Wd[i];
    }
    sb[tid] = bd[tid];
    __syncthreads();
    int mbase = blockIdx.x * 8;
    for (int mi = 0; mi < 8; mi++) {
        int m = mbase + mi;
        float acc = sb[tid];
        const float* dr = g_dbl + (size_t)m*48;
        #pragma unroll
        for (int r = 0; r < 16; r++) acc = fmaf(dr[r], sw[r*512 + tid], acc);
        g_dt[(size_t)m*512 + tid] = (acc > 20.f) ? acc : __logf(1.f + __expf(acc));
    }
}

// ---------------- scan phase 1 ----------------------------------------------
__global__ void scan1_kernel(const float* __restrict__ A_log) {
    __shared__ float sbc[2][32];
    int ch = blockIdx.x, b = blockIdx.y, g = blockIdx.z;
    int tid = threadIdx.x;
    int d = g*128 + tid;
    float a[16], h[16];
    #pragma unroll
    for (int n = 0; n < 16; n++) { a[n] = -expf(A_log[d*16 + n]); h[n] = 0.f; }
    int mbase = b*LSEQ + ch*CLEN;
    if (tid < 32) sbc[0][tid] = g_dbl[(size_t)mbase*48 + 16 + tid];
    float S = 0.f;
    float u   = g_xc[(size_t)mbase*512 + d];
    float dtv = g_dt[(size_t)mbase*512 + d];
    for (int i = 0; i < CLEN; i++) {
        __syncthreads();
        float u_n = 0.f, dt_n = 0.f;
        if (i < CLEN-1) {
            if (tid < 32) sbc[(i+1)&1][tid] = g_dbl[(size_t)(mbase+i+1)*48 + 16 + tid];
            u_n  = g_xc[(size_t)(mbase+i+1)*512 + d];
            dt_n = g_dt[(size_t)(mbase+i+1)*512 + d];
        }
        int m = mbase + i;
        S += dtv;
        g_dt[(size_t)m*512 + d] = S;
        float du = dtv * u;
        const float* sB = sbc[i&1];
        const float* sC = sbc[i&1] + 16;
        float y = 0.f;
        #pragma unroll
        for (int n = 0; n < 16; n++) {
            float dA = __expf(dtv * a[n]);
            h[n] = fmaf(h[n], dA, du * sB[n]);
            y = fmaf(h[n], sC[n], y);
        }
        g_y[(size_t)m*512 + d] = y;
        u = u_n; dtv = dt_n;
    }
    size_t base = (size_t)((b*NCHUNK + ch)*16) * 512 + d;
    #pragma unroll
    for (int n = 0; n < 16; n++) g_hend[base + (size_t)n*512] = h[n];
}

// ---------------- scan phase 2 ----------------------------------------------
__global__ void scan2_kernel(const float* __restrict__ A_log) {
    int n = blockIdx.x, b = blockIdx.y, d = threadIdx.x;
    float an = -expf(A_log[d*16 + n]);
    float hprev = 0.f;
    for (int ch = 0; ch < NCHUNK; ch++) {
        float Send = g_dt[(size_t)(b*LSEQ + ch*CLEN + CLEN-1)*512 + d];
        size_t idx = (size_t)((b*NCHUNK + ch)*16 + n)*512 + d;
        float tmp = g_hend[idx];
        g_hend[idx] = hprev;
        hprev = fmaf(__expf(an * Send), hprev, tmp);
    }
}

// ---------------- scan phase 3 ----------------------------------------------
__global__ void scan3_kernel(const float* __restrict__ A_log,
                             const float* __restrict__ Dp) {
    __shared__ float sc[2][16];
    int ch = blockIdx.x, b = blockIdx.y, g = blockIdx.z;
    int tid = threadIdx.x;
    int d = g*128 + tid;
    float a[16], hin[16];
    size_t hbase = (size_t)((b*NCHUNK + ch)*16) * 512 + d;
    #pragma unroll
    for (int n = 0; n < 16; n++) {
        a[n]   = -expf(A_log[d*16 + n]);
        hin[n] = g_hend[hbase + (size_t)n*512];
    }
    float Dd = Dp[d];
    int mbase = b*LSEQ + ch*CLEN;
    if (tid < 16) sc[0][tid] = g_dbl[(size_t)mbase*48 + 32 + tid];
    float S  = g_dt[(size_t)mbase*512 + d];
    float u  = g_xc[(size_t)mbase*512 + d];
    float z  = g_xz[(size_t)mbase*1024 + 512 + d];
    float yl = g_y[(size_t)mbase*512 + d];
    for (int i = 0; i < CLEN; i++) {
        __syncthreads();
        float S_n=0.f, u_n=0.f, z_n=0.f, yl_n=0.f;
        if (i < CLEN-1) {
            if (tid < 16) sc[(i+1)&1][tid] = g_dbl[(size_t)(mbase+i+1)*48 + 32 + tid];
            S_n  = g_dt[(size_t)(mbase+i+1)*512 + d];
            u_n  = g_xc[(size_t)(mbase+i+1)*512 + d];
            z_n  = g_xz[(size_t)(mbase+i+1)*1024 + 512 + d];
            yl_n = g_y[(size_t)(mbase+i+1)*512 + d];
        }
        int m = mbase + i;
        const float* C = sc[i&1];
        float yf = 0.f;
        #pragma unroll
        for (int n = 0; n < 16; n++)
            yf = fmaf(C[n] * __expf(a[n]*S), hin[n], yf);
        float y = yl + yf + u*Dd;
        y *= z / (1.f + __expf(-z));
        g_y[(size_t)m*512 + d] = y;
        S = S_n; u = u_n; z = z_n; yl = yl_n;
    }
}

// ---------------------------------------------------------------------------
extern "C" void kernel_launch(void* const* d_in, const int* in_sizes, int n_in,
                              void* d_out, int out_size) {
    const float* x         = (const float*)d_in[0];
    const float* norm_w    = (const float*)d_in[1];
    const float* norm_b    = (const float*)d_in[2];
    const float* in_proj_w = (const float*)d_in[3];
    const float* conv_w    = (const float*)d_in[4];
    const float* conv_b    = (const float*)d_in[5];
    const float* x_proj_w  = (const float*)d_in[6];
    const float* dt_proj_w = (const float*)d_in[7];
    const float* dt_proj_b = (const float*)d_in[8];
    const float* A_log     = (const float*)d_in[9];
    const float* D_ssm     = (const float*)d_in[10];
    const float* out_proj_w= (const float*)d_in[11];
    const float* proj_w    = (const float*)d_in[12];
    const float* proj_b    = (const float*)d_in[13];
    const float* skip      = (const float*)d_in[14];
    float* out = (float*)d_out;

    cudaFuncSetAttribute(gemm_mma<0,1024,256>, cudaFuncAttributeMaxDynamicSharedMemorySize, GEMM_SMEM);
    cudaFuncSetAttribute(gemm_mma<1,256,512>,  cudaFuncAttributeMaxDynamicSharedMemorySize, GEMM_SMEM);
    cudaFuncSetAttribute(gemm_mma<2,256,256>,  cudaFuncAttributeMaxDynamicSharedMemorySize, GEMM_SMEM);

    ln_kernel<<<512, 256>>>(x, norm_w, norm_b);
    gemm_mma<0,1024,256><<<dim3(8,128), 256, GEMM_SMEM>>>(in_proj_w, nullptr, nullptr);
    conv_kernel<<<2048, 512>>>(conv_w, conv_b);
    xproj_kernel<<<256, 128>>>(x_proj_w);
    dt_kernel<<<2048, 512>>>(dt_proj_w, dt_proj_b);
    scan1_kernel<<<dim3(NCHUNK,BSZ,4), 128>>>(A_log);
    scan2_kernel<<<dim3(16,BSZ), 512>>>(A_log);
    scan3_kernel<<<dim3(NCHUNK,BSZ,4), 128>>>(A_log, D_ssm);
    gemm_mma<1,256,512><<<dim3(2,128), 256, GEMM_SMEM>>>(out_proj_w, nullptr, skip);
    gemm_mma<2,256,256><<<dim3(2,128), 256, GEMM_SMEM>>>(proj_w, proj_b, nullptr);
    outtr_kernel<<<dim3(128,8,4), 256>>>(out);
}

// round 6
// speedup vs baseline: 1.9020x; 1.1695x over previous
#include <cuda_runtime.h>
#include <cuda_bf16.h>
#include <math.h>
#include <stdint.h>

#define BSZ 4
#define LSEQ 4096
#define DM 256
#define DI 512
#define MTOT (BSZ*LSEQ)        // 16384
#define NCHUNK 64
#define CLEN 64

// ---------------- scratch (device globals; no allocations allowed) ---------
__device__ float g_xn[MTOT*DM];
__device__ float g_xf[MTOT*DM];
__device__ float g_xz[MTOT*2*DI];
__device__ float g_xc[MTOT*DI];
__device__ float g_dbl[MTOT*48];
__device__ float g_dt[MTOT*DI];          // chunk-inclusive prefix sums of dt
__device__ float g_y[MTOT*DI];
__device__ float g_xm[MTOT*DM];
__device__ float g_hend[BSZ*NCHUNK*16*DI];

// ---------------- helpers ----------------------------------------------------
__device__ __forceinline__ uint32_t smem_u32(const void* p) {
    uint32_t a;
    asm("{ .reg .u64 t; cvta.to.shared.u64 t, %1; cvt.u32.u64 %0, t; }" : "=r"(a) : "l"(p));
    return a;
}
__device__ __forceinline__ void split4(float4 v, uint2& h, uint2& l) {
    __nv_bfloat16 h0 = __float2bfloat16(v.x), h1 = __float2bfloat16(v.y);
    __nv_bfloat16 h2 = __float2bfloat16(v.z), h3 = __float2bfloat16(v.w);
    float r0 = v.x - __bfloat162float(h0), r1 = v.y - __bfloat162float(h1);
    float r2 = v.z - __bfloat162float(h2), r3 = v.w - __bfloat162float(h3);
    __nv_bfloat16 l0 = __float2bfloat16(r0), l1 = __float2bfloat16(r1);
    __nv_bfloat16 l2 = __float2bfloat16(r2), l3 = __float2bfloat16(r3);
    h.x = ((uint32_t)__bfloat16_as_ushort(h1) << 16) | __bfloat16_as_ushort(h0);
    h.y = ((uint32_t)__bfloat16_as_ushort(h3) << 16) | __bfloat16_as_ushort(h2);
    l.x = ((uint32_t)__bfloat16_as_ushort(l1) << 16) | __bfloat16_as_ushort(l0);
    l.y = ((uint32_t)__bfloat16_as_ushort(l3) << 16) | __bfloat16_as_ushort(l2);
}
__device__ __forceinline__ void ldm4(uint32_t* r, uint32_t addr) {
    asm volatile("ldmatrix.sync.aligned.m8n8.x4.shared.b16 {%0,%1,%2,%3}, [%4];"
        : "=r"(r[0]), "=r"(r[1]), "=r"(r[2]), "=r"(r[3]) : "r"(addr));
}
__device__ __forceinline__ void mma16816(float* c, const uint32_t* a,
                                         uint32_t b0, uint32_t b1) {
    asm volatile(
        "mma.sync.aligned.m16n8k16.row.col.f32.bf16.bf16.f32 "
        "{%0,%1,%2,%3}, {%4,%5,%6,%7}, {%8,%9}, {%0,%1,%2,%3};"
        : "+f"(c[0]), "+f"(c[1]), "+f"(c[2]), "+f"(c[3])
        : "r"(a[0]), "r"(a[1]), "r"(a[2]), "r"(a[3]), "r"(b0), "r"(b1));
}

// ======== warp-MMA GEMM: C = A @ W^T, 128x128 CTA tile, split-bf16 x3 =======
// MODE 0: A=g_xn (K=256) -> g_xz (N=1024)
// MODE 1: A=g_y  (K=512) -> g_xm = acc + skip*g_xf (N=256)
// MODE 2: A=g_xm (K=256) -> outp[(b*256+n)*4096+l] = acc + bias[n] (fused transpose)
#define GSTAGE 40960
#define GEMM_SMEM 81920
#define KC 32
#define SROW 80

template<int MODE, int N, int K>
__global__ __launch_bounds__(256)
void gemm_mma(const float* __restrict__ W, const float* __restrict__ extra,
              const float* __restrict__ skipPtr, float* __restrict__ outp) {
    extern __shared__ char sm[];
    const float* A = (MODE == 0) ? g_xn : (MODE == 1) ? g_y : g_xm;
    uint32_t sbase = smem_u32(sm);
    int tid = threadIdx.x, wid = tid >> 5, lane = tid & 31;
    int warp_m = wid & 3, warp_n = wid >> 2;
    int m0 = blockIdx.y * 128, n0 = blockIdx.x * 128;

    float acc[2][8][4];
    #pragma unroll
    for (int mt = 0; mt < 2; mt++)
        #pragma unroll
        for (int nt = 0; nt < 8; nt++)
            #pragma unroll
            for (int q = 0; q < 4; q++) acc[mt][nt][q] = 0.f;

    float4 ra[4], rb[4];
    const int row_ld = tid >> 3;
    const int c4 = (tid & 7) << 2;

    #pragma unroll
    for (int t = 0; t < 4; t++) {
        int row = row_ld + t * 32;
        ra[t] = *(const float4*)&A[(size_t)(m0 + row) * K + c4];
        rb[t] = *(const float4*)&W[(size_t)(n0 + row) * K + c4];
    }
    #pragma unroll
    for (int t = 0; t < 4; t++) {
        int row = row_ld + t * 32;
        uint2 h, l;
        split4(ra[t], h, l);
        *(uint2*)(sm + row * SROW + c4 * 2) = h;
        *(uint2*)(sm + 10240 + row * SROW + c4 * 2) = l;
        split4(rb[t], h, l);
        *(uint2*)(sm + 20480 + row * SROW + c4 * 2) = h;
        *(uint2*)(sm + 30720 + row * SROW + c4 * 2) = l;
    }

    const int NKC = K / KC;
    const int a_row = (lane & 7) + ((lane >> 3) & 1) * 8;
    const int a_koff = ((lane >> 4) & 1) * 16;
    const int b_row = (lane & 7) + ((lane >> 4) & 1) * 8;
    const int b_koff = ((lane >> 3) & 1) * 16;

    for (int kc = 0; kc < NKC; kc++) {
        __syncthreads();
        if (kc + 1 < NKC) {
            int k0 = (kc + 1) * KC;
            #pragma unroll
            for (int t = 0; t < 4; t++) {
                int row = row_ld + t * 32;
                ra[t] = *(const float4*)&A[(size_t)(m0 + row) * K + k0 + c4];
                rb[t] = *(const float4*)&W[(size_t)(n0 + row) * K + k0 + c4];
            }
        }
        uint32_t aB = sbase + (kc & 1) * GSTAGE;
        uint32_t bB = aB + 20480;
        #pragma unroll
        for (int kk = 0; kk < 2; kk++) {
            uint32_t Ah[2][4], Al[2][4], Bh[4][4], Bl[4][4];
            #pragma unroll
            for (int mt = 0; mt < 2; mt++) {
                uint32_t addr = aB + (uint32_t)((warp_m * 32 + mt * 16 + a_row) * SROW
                                               + kk * 32 + a_koff);
                ldm4(Ah[mt], addr);
                ldm4(Al[mt], addr + 10240);
            }
            #pragma unroll
            for (int np = 0; np < 4; np++) {
                uint32_t addr = bB + (uint32_t)((warp_n * 64 + np * 16 + b_row) * SROW
                                               + kk * 32 + b_koff);
                ldm4(Bh[np], addr);
                ldm4(Bl[np], addr + 10240);
            }
            #pragma unroll
            for (int mt = 0; mt < 2; mt++)
                #pragma unroll
                for (int nt = 0; nt < 8; nt++) {
                    int np = nt >> 1, o = (nt & 1) * 2;
                    mma16816(acc[mt][nt], Ah[mt], Bh[np][o], Bh[np][o + 1]);
                    mma16816(acc[mt][nt], Ah[mt], Bl[np][o], Bl[np][o + 1]);
                    mma16816(acc[mt][nt], Al[mt], Bh[np][o], Bh[np][o + 1]);
                }
        }
        if (kc + 1 < NKC) {
            char* dst = sm + ((kc + 1) & 1) * GSTAGE;
            #pragma unroll
            for (int t = 0; t < 4; t++) {
                int row = row_ld + t * 32;
                uint2 h, l;
                split4(ra[t], h, l);
                *(uint2*)(dst + row * SROW + c4 * 2) = h;
                *(uint2*)(dst + 10240 + row * SROW + c4 * 2) = l;
                split4(rb[t], h, l);
                *(uint2*)(dst + 20480 + row * SROW + c4 * 2) = h;
                *(uint2*)(dst + 30720 + row * SROW + c4 * 2) = l;
            }
        }
    }

    if (MODE == 2) {
        // stage accumulator tile in smem, then write (B,C,L) coalesced
        float* stage = (float*)sm;
        __syncthreads();
        #pragma unroll
        for (int mt = 0; mt < 2; mt++)
            #pragma unroll
            for (int nt = 0; nt < 8; nt++) {
                int rl = warp_m * 32 + mt * 16 + (lane >> 2);
                int cl = warp_n * 64 + nt * 8 + (lane & 3) * 2;
                stage[rl * 129 + cl]       = acc[mt][nt][0];
                stage[rl * 129 + cl + 1]   = acc[mt][nt][1];
                stage[(rl+8) * 129 + cl]   = acc[mt][nt][2];
                stage[(rl+8) * 129 + cl+1] = acc[mt][nt][3];
            }
        __syncthreads();
        int b = m0 >> 12, l0q = m0 & 4095;
        int tx = tid & 127, cy = tid >> 7;
        for (int c = cy; c < 128; c += 2) {
            float v = stage[tx * 129 + c] + extra[n0 + c];
            outp[(size_t)(b * 256 + n0 + c) * 4096 + l0q + tx] = v;
        }
        return;
    }

    float skip = (MODE == 1) ? skipPtr[0] : 0.f;
    #pragma unroll
    for (int mt = 0; mt < 2; mt++) {
        #pragma unroll
        for (int nt = 0; nt < 8; nt++) {
            int row = m0 + warp_m * 32 + mt * 16 + (lane >> 2);
            int col = n0 + warp_n * 64 + nt * 8 + (lane & 3) * 2;
            float2 v0 = make_float2(acc[mt][nt][0], acc[mt][nt][1]);
            float2 v1 = make_float2(acc[mt][nt][2], acc[mt][nt][3]);
            if (MODE == 0) {
                *(float2*)&g_xz[(size_t)row * N + col] = v0;
                *(float2*)&g_xz[(size_t)(row + 8) * N + col] = v1;
            } else {
                float2 f0 = *(const float2*)&g_xf[(size_t)row * 256 + col];
                float2 f1 = *(const float2*)&g_xf[(size_t)(row + 8) * 256 + col];
                v0.x += skip * f0.x; v0.y += skip * f0.y;
                v1.x += skip * f1.x; v1.y += skip * f1.y;
                *(float2*)&g_xm[(size_t)row * 256 + col] = v0;
                *(float2*)&g_xm[(size_t)(row + 8) * 256 + col] = v1;
            }
        }
    }
}

// ======== x_proj as warp-MMA: dbl = xc @ x_proj_w^T (N=48 padded to 64) =====
// 128m x 64n CTA tile, 8 warps (4m x 2n), warp tile 32m x 32n.
#define XSTAGE 30720
#define XPROJ_SMEM 61440
__global__ __launch_bounds__(256)
void xproj_mma(const float* __restrict__ W) {
    extern __shared__ char sm[];
    uint32_t sbase = smem_u32(sm);
    int tid = threadIdx.x, wid = tid >> 5, lane = tid & 31;
    int warp_m = wid & 3, warp_n = wid >> 2;
    int m0 = blockIdx.x * 128;
    const int K = 512;

    float acc[2][4][4];
    #pragma unroll
    for (int mt = 0; mt < 2; mt++)
        #pragma unroll
        for (int nt = 0; nt < 4; nt++)
            #pragma unroll
            for (int q = 0; q < 4; q++) acc[mt][nt][q] = 0.f;

    float4 ra[4], rb[2];
    const int row_ld = tid >> 3;
    const int c4 = (tid & 7) << 2;

    #pragma unroll
    for (int t = 0; t < 4; t++)
        ra[t] = *(const float4*)&g_xc[(size_t)(m0 + row_ld + t * 32) * K + c4];
    #pragma unroll
    for (int t = 0; t < 2; t++) {
        int row = row_ld + t * 32;
        rb[t] = (row < 48) ? *(const float4*)&W[(size_t)row * K + c4]
                           : make_float4(0.f, 0.f, 0.f, 0.f);
    }
    #pragma unroll
    for (int t = 0; t < 4; t++) {
        int row = row_ld + t * 32;
        uint2 h, l;
        split4(ra[t], h, l);
        *(uint2*)(sm + row * SROW + c4 * 2) = h;
        *(uint2*)(sm + 10240 + row * SROW + c4 * 2) = l;
    }
    #pragma unroll
    for (int t = 0; t < 2; t++) {
        int row = row_ld + t * 32;
        uint2 h, l;
        split4(rb[t], h, l);
        *(uint2*)(sm + 20480 + row * SROW + c4 * 2) = h;
        *(uint2*)(sm + 25600 + row * SROW + c4 * 2) = l;
    }

    const int NKC = K / KC;  // 16
    const int a_row = (lane & 7) + ((lane >> 3) & 1) * 8;
    const int a_koff = ((lane >> 4) & 1) * 16;
    const int b_row = (lane & 7) + ((lane >> 4) & 1) * 8;
    const int b_koff = ((lane >> 3) & 1) * 16;

    for (int kc = 0; kc < NKC; kc++) {
        __syncthreads();
        if (kc + 1 < NKC) {
            int k0 = (kc + 1) * KC;
            #pragma unroll
            for (int t = 0; t < 4; t++)
                ra[t] = *(const float4*)&g_xc[(size_t)(m0 + row_ld + t * 32) * K + k0 + c4];
            #pragma unroll
            for (int t = 0; t < 2; t++) {
                int row = row_ld + t * 32;
                rb[t] = (row < 48) ? *(const float4*)&W[(size_t)row * K + k0 + c4]
                                   : make_float4(0.f, 0.f, 0.f, 0.f);
            }
        }
        uint32_t aB = sbase + (kc & 1) * XSTAGE;
        uint32_t bB = aB + 20480;
        #pragma unroll
        for (int kk = 0; kk < 2; kk++) {
            uint32_t Ah[2][4], Al[2][4], Bh[2][4], Bl[2][4];
            #pragma unroll
            for (int mt = 0; mt < 2; mt++) {
                uint32_t addr = aB + (uint32_t)((warp_m * 32 + mt * 16 + a_row) * SROW
                                               + kk * 32 + a_koff);
                ldm4(Ah[mt], addr);
                ldm4(Al[mt], addr + 10240);
            }
            #pragma unroll
            for (int np = 0; np < 2; np++) {
                uint32_t addr = bB + (uint32_t)((warp_n * 32 + np * 16 + b_row) * SROW
                                               + kk * 32 + b_koff);
                ldm4(Bh[np], addr);
                ldm4(Bl[np], addr + 5120);
            }
            #pragma unroll
            for (int mt = 0; mt < 2; mt++)
                #pragma unroll
                for (int nt = 0; nt < 4; nt++) {
                    int np = nt >> 1, o = (nt & 1) * 2;
                    mma16816(acc[mt][nt], Ah[mt], Bh[np][o], Bh[np][o + 1]);
                    mma16816(acc[mt][nt], Ah[mt], Bl[np][o], Bl[np][o + 1]);
                    mma16816(acc[mt][nt], Al[mt], Bh[np][o], Bh[np][o + 1]);
                }
        }
        if (kc + 1 < NKC) {
            char* dst = sm + ((kc + 1) & 1) * XSTAGE;
            #pragma unroll
            for (int t = 0; t < 4; t++) {
                int row = row_ld + t * 32;
                uint2 h, l;
                split4(ra[t], h, l);
                *(uint2*)(dst + row * SROW + c4 * 2) = h;
                *(uint2*)(dst + 10240 + row * SROW + c4 * 2) = l;
            }
            #pragma unroll
            for (int t = 0; t < 2; t++) {
                int row = row_ld + t * 32;
                uint2 h, l;
                split4(rb[t], h, l);
                *(uint2*)(dst + 20480 + row * SROW + c4 * 2) = h;
                *(uint2*)(dst + 25600 + row * SROW + c4 * 2) = l;
            }
        }
    }

    #pragma unroll
    for (int mt = 0; mt < 2; mt++)
        #pragma unroll
        for (int nt = 0; nt < 4; nt++) {
            int row = m0 + warp_m * 32 + mt * 16 + (lane >> 2);
            int col = warp_n * 32 + nt * 8 + (lane & 3) * 2;
            if (col < 48) {
                *(float2*)&g_dbl[(size_t)row * 48 + col] =
                    make_float2(acc[mt][nt][0], acc[mt][nt][1]);
                *(float2*)&g_dbl[(size_t)(row + 8) * 48 + col] =
                    make_float2(acc[mt][nt][2], acc[mt][nt][3]);
            }
        }
}

// ---------------- LayerNorm -------------------------------------------------
__global__ void ln_kernel(const float* __restrict__ x,
                          const float* __restrict__ nw,
                          const float* __restrict__ nb) {
    __shared__ float s[256*33];
    __shared__ float ps[8][33], pq[8][33];
    __shared__ float s_mu[32], s_rs[32];
    int blk = blockIdx.x;
    int b  = blk >> 7;
    int l0 = (blk & 127) * 32;
    int tid = threadIdx.x;
    int lx = tid & 31, cy = tid >> 5;
    const float* xb = x + (size_t)b * DM * LSEQ;
    #pragma unroll 4
    for (int cb = 0; cb < 256; cb += 8) {
        int c = cb + cy;
        s[c*33 + lx] = xb[(size_t)c * LSEQ + l0 + lx];
    }
    __syncthreads();
    {
        float sum = 0.f, sq = 0.f;
        int c0 = cy * 32;
        #pragma unroll 8
        for (int c = c0; c < c0 + 32; c++) { float v = s[c*33 + lx]; sum += v; sq += v*v; }
        ps[cy][lx] = sum; pq[cy][lx] = sq;
    }
    __syncthreads();
    if (tid < 32) {
        float sum = 0.f, sq = 0.f;
        #pragma unroll
        for (int p = 0; p < 8; p++) { sum += ps[p][tid]; sq += pq[p][tid]; }
        float mu = sum * (1.f/256.f);
        float var = sq * (1.f/256.f) - mu*mu;
        s_mu[tid] = mu;
        s_rs[tid] = rsqrtf(var + 1e-5f);
    }
    __syncthreads();
    for (int j = tid; j < 32*256; j += 256) {
        int ll = j >> 8, c = j & 255;
        float v = s[c*33 + ll];
        size_t idx = (size_t)(b*LSEQ + l0 + ll)*DM + c;
        g_xf[idx] = v;
        g_xn[idx] = (v - s_mu[ll]) * s_rs[ll] * nw[c] + nb[c];
    }
}

// ---------------- depthwise causal conv (k=4) + SiLU ------------------------
__global__ void conv_kernel(const float* __restrict__ cw, const float* __restrict__ cb) {
    int d = threadIdx.x;
    int m0 = blockIdx.x * 8;
    int l0 = m0 & 4095;
    float w0 = cw[d*4+0], w1 = cw[d*4+1], w2 = cw[d*4+2], w3 = cw[d*4+3];
    float bias = cb[d];
    float r[11];
    #pragma unroll
    for (int i = 0; i < 11; i++) {
        int off = i - 3;
        r[i] = (l0 + off >= 0) ? g_xz[(size_t)(m0 + off)*1024 + d] : 0.f;
    }
    #pragma unroll
    for (int j = 0; j < 8; j++) {
        float acc = bias;
        acc = fmaf(r[j],   w0, acc);
        acc = fmaf(r[j+1], w1, acc);
        acc = fmaf(r[j+2], w2, acc);
        acc = fmaf(r[j+3], w3, acc);
        float sg = 1.f / (1.f + __expf(-acc));
        g_xc[(size_t)(m0+j)*512 + d] = acc * sg;
    }
}

// ---------------- scan phase 1: dt-proj + softplus + local recurrence -------
__global__ void scan1_kernel(const float* __restrict__ A_log,
                             const float* __restrict__ Wd,
                             const float* __restrict__ bdp) {
    __shared__ float sd[64*48];
    int ch = blockIdx.x, b = blockIdx.y, g = blockIdx.z;
    int tid = threadIdx.x;            // 128
    int d = g*128 + tid;
    int mbase = b*LSEQ + ch*CLEN;
    #pragma unroll
    for (int j = 0; j < 24; j++)
        sd[tid + j*128] = g_dbl[(size_t)mbase*48 + tid + j*128];
    float a[16], h[16], wd[16];
    #pragma unroll
    for (int n = 0; n < 16; n++) { a[n] = -expf(A_log[d*16 + n]); h[n] = 0.f; }
    #pragma unroll
    for (int q = 0; q < 4; q++) {
        float4 v = *(const float4*)&Wd[(size_t)d*16 + q*4];
        wd[q*4+0] = v.x; wd[q*4+1] = v.y; wd[q*4+2] = v.z; wd[q*4+3] = v.w;
    }
    float bd_ = bdp[d];
    __syncthreads();
    float S = 0.f;
    float u = g_xc[(size_t)mbase*512 + d];
    for (int i = 0; i < CLEN; i++) {
        float u_n = (i < CLEN-1) ? g_xc[(size_t)(mbase+i+1)*512 + d] : 0.f;
        const float* row = sd + i*48;
        float araw = bd_;
        #pragma unroll
        for (int r = 0; r < 16; r++) araw = fmaf(row[r], wd[r], araw);
        float dtv = (araw > 20.f) ? araw : __logf(1.f + __expf(araw));
        S += dtv;
        g_dt[(size_t)(mbase+i)*512 + d] = S;
        float du = dtv * u;
        float y = 0.f;
        #pragma unroll
        for (int n = 0; n < 16; n++) {
            float dA = __expf(dtv * a[n]);
            h[n] = fmaf(h[n], dA, du * row[16+n]);
            y = fmaf(h[n], row[32+n], y);
        }
        g_y[(size_t)(mbase+i)*512 + d] = y;
        u = u_n;
    }
    size_t base = (size_t)((b*NCHUNK + ch)*16) * 512 + d;
    #pragma unroll
    for (int n = 0; n < 16; n++) g_hend[base + (size_t)n*512] = h[n];
}

// ---------------- scan phase 2: propagate states across chunks --------------
__global__ void scan2_kernel(const float* __restrict__ A_log) {
    int n = blockIdx.x, b = blockIdx.y, d = threadIdx.x;
    float an = -expf(A_log[d*16 + n]);
    float hprev = 0.f;
    for (int ch = 0; ch < NCHUNK; ch++) {
        float Send = g_dt[(size_t)(b*LSEQ + ch*CLEN + CLEN-1)*512 + d];
        size_t idx = (size_t)((b*NCHUNK + ch)*16 + n)*512 + d;
        float tmp = g_hend[idx];
        g_hend[idx] = hprev;
        hprev = fmaf(__expf(an * Send), hprev, tmp);
    }
}

// ---------------- scan phase 3: fix-up + D skip + z gating ------------------
__global__ void scan3_kernel(const float* __restrict__ A_log,
                             const float* __restrict__ Dp) {
    __shared__ float sc[64*16];
    int ch = blockIdx.x, b = blockIdx.y, g = blockIdx.z;
    int tid = threadIdx.x;
    int d = g*128 + tid;
    int mbase = b*LSEQ + ch*CLEN;
    #pragma unroll
    for (int j = 0; j < 8; j++) {
        int idx = tid + j*128;
        sc[idx] = g_dbl[(size_t)(mbase + (idx >> 4))*48 + 32 + (idx & 15)];
    }
    float a[16], hin[16];
    size_t hbase = (size_t)((b*NCHUNK + ch)*16) * 512 + d;
    #pragma unroll
    for (int n = 0; n < 16; n++) {
        a[n]   = -expf(A_log[d*16 + n]);
        hin[n] = g_hend[hbase + (size_t)n*512];
    }
    float Dd = Dp[d];
    __syncthreads();
    float S  = g_dt[(size_t)mbase*512 + d];
    float u  = g_xc[(size_t)mbase*512 + d];
    float z  = g_xz[(size_t)mbase*1024 + 512 + d];
    float yl = g_y[(size_t)mbase*512 + d];
    for (int i = 0; i < CLEN; i++) {
        float S_n=0.f, u_n=0.f, z_n=0.f, yl_n=0.f;
        if (i < CLEN-1) {
            S_n  = g_dt[(size_t)(mbase+i+1)*512 + d];
            u_n  = g_xc[(size_t)(mbase+i+1)*512 + d];
            z_n  = g_xz[(size_t)(mbase+i+1)*1024 + 512 + d];
            yl_n = g_y[(size_t)(mbase+i+1)*512 + d];
        }
        const float* C = sc + i*16;
        float yf = 0.f;
        #pragma unroll
        for (int n = 0; n < 16; n++)
            yf = fmaf(C[n] * __expf(a[n]*S), hin[n], yf);
        float y = yl + yf + u*Dd;
        y *= z / (1.f + __expf(-z));
        g_y[(size_t)(mbase+i)*512 + d] = y;
        S = S_n; u = u_n; z = z_n; yl = yl_n;
    }
}

// ---------------------------------------------------------------------------
extern "C" void kernel_launch(void* const* d_in, const int* in_sizes, int n_in,
                              void* d_out, int out_size) {
    const float* x         = (const float*)d_in[0];
    const float* norm_w    = (const float*)d_in[1];
    const float* norm_b    = (const float*)d_in[2];
    const float* in_proj_w = (const float*)d_in[3];
    const float* conv_w    = (const float*)d_in[4];
    const float* conv_b    = (const float*)d_in[5];
    const float* x_proj_w  = (const float*)d_in[6];
    const float* dt_proj_w = (const float*)d_in[7];
    const float* dt_proj_b = (const float*)d_in[8];
    const float* A_log     = (const float*)d_in[9];
    const float* D_ssm     = (const float*)d_in[10];
    const float* out_proj_w= (const float*)d_in[11];
    const float* proj_w    = (const float*)d_in[12];
    const float* proj_b    = (const float*)d_in[13];
    const float* skip      = (const float*)d_in[14];
    float* out = (float*)d_out;

    cudaFuncSetAttribute(gemm_mma<0,1024,256>, cudaFuncAttributeMaxDynamicSharedMemorySize, GEMM_SMEM);
    cudaFuncSetAttribute(gemm_mma<1,256,512>,  cudaFuncAttributeMaxDynamicSharedMemorySize, GEMM_SMEM);
    cudaFuncSetAttribute(gemm_mma<2,256,256>,  cudaFuncAttributeMaxDynamicSharedMemorySize, GEMM_SMEM);
    cudaFuncSetAttribute(xproj_mma, cudaFuncAttributeMaxDynamicSharedMemorySize, XPROJ_SMEM);

    ln_kernel<<<512, 256>>>(x, norm_w, norm_b);
    gemm_mma<0,1024,256><<<dim3(8,128), 256, GEMM_SMEM>>>(in_proj_w, nullptr, nullptr, nullptr);
    conv_kernel<<<2048, 512>>>(conv_w, conv_b);
    xproj_mma<<<128, 256, XPROJ_SMEM>>>(x_proj_w);
    scan1_kernel<<<dim3(NCHUNK,BSZ,4), 128>>>(A_log, dt_proj_w, dt_proj_b);
    scan2_kernel<<<dim3(16,BSZ), 512>>>(A_log);
    scan3_kernel<<<dim3(NCHUNK,BSZ,4), 128>>>(A_log, D_ssm);
    gemm_mma<1,256,512><<<dim3(2,128), 256, GEMM_SMEM>>>(out_proj_w, nullptr, skip, nullptr);
    gemm_mma<2,256,256><<<dim3(2,128), 256, GEMM_SMEM>>>(proj_w, proj_b, nullptr, out);
}